// round 1
// baseline (speedup 1.0000x reference)
#include <cuda_runtime.h>
#include <cuda_bf16.h>
#include <math_constants.h>

// Problem constants (fixed by reference setup_inputs)
#define BATCH   2
#define SEQ     4096
#define DMODEL  768
#define NHEADS  12
#define DHEAD   64
#define BT      (BATCH * SEQ)        // 8192
#define C3      (3 * DMODEL)         // 2304

// Scratch (device globals: allocation-free per harness rules)
__device__ float g_qkv[(size_t)BT * C3];     // [B*T, 3C]
__device__ float g_att[(size_t)BT * DMODEL]; // [B*T, C] attention output (pre-proj)

// ---------------------------------------------------------------------------
// SGEMM: C[M,N] = A[M,K] @ B[K,N] + bias[N]
// 128x128 block tile, BK=8, 256 threads, 8x8 microtile per thread.
// Requires M%128==0, N%128==0, K%8==0 (holds: 8192, 2304/768, 768).
// ---------------------------------------------------------------------------
#define BM 128
#define BN 128
#define BK 8

__global__ __launch_bounds__(256)
void sgemm_bias_kernel(const float* __restrict__ A,
                       const float* __restrict__ B,
                       const float* __restrict__ bias,
                       float* __restrict__ Cmat,
                       int M, int N, int K)
{
    __shared__ float As[BK][BM];
    __shared__ float Bs[BK][BN];

    const int tid  = threadIdx.x;
    const int brow = blockIdx.y * BM;
    const int bcol = blockIdx.x * BN;

    // A loading: each thread one float4 (128 rows x 2 float4 = 256 loads)
    const int a_row = tid >> 1;            // 0..127
    const int a_col = (tid & 1) * 4;       // 0 or 4
    // B loading: each thread one float4 (8 rows x 32 float4 = 256 loads)
    const int b_row = tid >> 5;            // 0..7
    const int b_col = (tid & 31) * 4;      // 0..124

    const int t_row = (tid >> 4) * 8;      // 0..120
    const int t_col = (tid & 15) * 8;      // 0..120

    float acc[8][8];
    #pragma unroll
    for (int i = 0; i < 8; i++)
        #pragma unroll
        for (int j = 0; j < 8; j++) acc[i][j] = 0.f;

    for (int k0 = 0; k0 < K; k0 += BK) {
        float4 av = *reinterpret_cast<const float4*>(
            &A[(size_t)(brow + a_row) * K + k0 + a_col]);
        float4 bv = *reinterpret_cast<const float4*>(
            &B[(size_t)(k0 + b_row) * N + bcol + b_col]);

        As[a_col + 0][a_row] = av.x;
        As[a_col + 1][a_row] = av.y;
        As[a_col + 2][a_row] = av.z;
        As[a_col + 3][a_row] = av.w;
        *reinterpret_cast<float4*>(&Bs[b_row][b_col]) = bv;
        __syncthreads();

        #pragma unroll
        for (int k = 0; k < BK; k++) {
            float af[8], bf[8];
            #pragma unroll
            for (int i = 0; i < 8; i++) af[i] = As[k][t_row + i];
            #pragma unroll
            for (int j = 0; j < 8; j++) bf[j] = Bs[k][t_col + j];
            #pragma unroll
            for (int i = 0; i < 8; i++)
                #pragma unroll
                for (int j = 0; j < 8; j++)
                    acc[i][j] += af[i] * bf[j];
        }
        __syncthreads();
    }

    #pragma unroll
    for (int i = 0; i < 8; i++) {
        #pragma unroll
        for (int j = 0; j < 8; j += 4) {
            float4 v;
            v.x = acc[i][j + 0] + bias[bcol + t_col + j + 0];
            v.y = acc[i][j + 1] + bias[bcol + t_col + j + 1];
            v.z = acc[i][j + 2] + bias[bcol + t_col + j + 2];
            v.w = acc[i][j + 3] + bias[bcol + t_col + j + 3];
            *reinterpret_cast<float4*>(
                &Cmat[(size_t)(brow + t_row + i) * N + bcol + t_col + j]) = v;
        }
    }
}

// ---------------------------------------------------------------------------
// Flash attention (causal), fp32, online softmax.
// grid = (T/64, H, B), block = 64 threads; thread t owns query row qt*64+t.
// K/V tiles 64x64 staged in shared memory. Causal exact: kt <= qt, and on the
// diagonal tile jmax = tid+1.
// ---------------------------------------------------------------------------
__global__ __launch_bounds__(64)
void flash_attn_kernel(const float* __restrict__ qkv, float* __restrict__ out)
{
    __shared__ float Ks[64][64];
    __shared__ float Vs[64][64];

    const int qt = (int)gridDim.x - 1 - (int)blockIdx.x;  // heavy tiles first
    const int h  = blockIdx.y;
    const int b  = blockIdx.z;
    const int tid = threadIdx.x;

    const int   qrow  = qt * 64 + tid;
    const float scale = 0.125f; // 1/sqrt(64)

    // Load this thread's query row into registers
    float q[64];
    {
        const float4* qp = reinterpret_cast<const float4*>(
            qkv + (size_t)(b * SEQ + qrow) * C3 + h * DHEAD);
        #pragma unroll
        for (int d4 = 0; d4 < 16; d4++) {
            float4 v = qp[d4];
            q[4 * d4 + 0] = v.x; q[4 * d4 + 1] = v.y;
            q[4 * d4 + 2] = v.z; q[4 * d4 + 3] = v.w;
        }
    }

    float o[64];
    #pragma unroll
    for (int d = 0; d < 64; d++) o[d] = 0.f;
    float m = -CUDART_INF_F;
    float l = 0.f;

    for (int kt = 0; kt <= qt; kt++) {
        __syncthreads();
        // Cooperative coalesced load of K and V 64x64 tiles
        #pragma unroll
        for (int it = 0; it < 16; it++) {
            int idx = it * 64 + tid;       // 0..1023
            int row = idx >> 4;            // 0..63
            int c4  = idx & 15;            // 0..15
            const float4* kp = reinterpret_cast<const float4*>(
                qkv + (size_t)(b * SEQ + kt * 64 + row) * C3 + DMODEL + h * DHEAD);
            const float4* vp = reinterpret_cast<const float4*>(
                qkv + (size_t)(b * SEQ + kt * 64 + row) * C3 + 2 * DMODEL + h * DHEAD);
            reinterpret_cast<float4*>(Ks[row])[c4] = kp[c4];
            reinterpret_cast<float4*>(Vs[row])[c4] = vp[c4];
        }
        __syncthreads();

        const int jmax = (kt == qt) ? (tid + 1) : 64;
        for (int j = 0; j < jmax; j++) {
            // s = scale * <q, K[j]>
            const float4* kj = reinterpret_cast<const float4*>(Ks[j]);
            float s = 0.f;
            #pragma unroll
            for (int d4 = 0; d4 < 16; d4++) {
                float4 kv = kj[d4];
                s += q[4 * d4 + 0] * kv.x;
                s += q[4 * d4 + 1] * kv.y;
                s += q[4 * d4 + 2] * kv.z;
                s += q[4 * d4 + 3] * kv.w;
            }
            s *= scale;

            if (s > m) {             // rare after warmup: O(ln T) per row
                float corr = __expf(m - s);   // m=-inf -> 0
                l *= corr;
                #pragma unroll
                for (int d = 0; d < 64; d++) o[d] *= corr;
                m = s;
            }
            float p = __expf(s - m);
            l += p;

            const float4* vj = reinterpret_cast<const float4*>(Vs[j]);
            #pragma unroll
            for (int d4 = 0; d4 < 16; d4++) {
                float4 vv = vj[d4];
                o[4 * d4 + 0] += p * vv.x;
                o[4 * d4 + 1] += p * vv.y;
                o[4 * d4 + 2] += p * vv.z;
                o[4 * d4 + 3] += p * vv.w;
            }
        }
    }

    const float inv = 1.f / l;
    float4* op = reinterpret_cast<float4*>(
        out + (size_t)(b * SEQ + qrow) * DMODEL + h * DHEAD);
    #pragma unroll
    for (int d4 = 0; d4 < 16; d4++) {
        float4 v;
        v.x = o[4 * d4 + 0] * inv;
        v.y = o[4 * d4 + 1] * inv;
        v.z = o[4 * d4 + 2] * inv;
        v.w = o[4 * d4 + 3] * inv;
        op[d4] = v;
    }
}

// ---------------------------------------------------------------------------
// Launch
// ---------------------------------------------------------------------------
extern "C" void kernel_launch(void* const* d_in, const int* in_sizes, int n_in,
                              void* d_out, int out_size)
{
    const float* x      = (const float*)d_in[0];
    const float* W_qkv  = (const float*)d_in[1];
    const float* b_qkv  = (const float*)d_in[2];
    const float* W_proj = (const float*)d_in[3];
    const float* b_proj = (const float*)d_in[4];
    float* out = (float*)d_out;

    void* p_qkv = nullptr;
    void* p_att = nullptr;
    cudaGetSymbolAddress(&p_qkv, g_qkv);
    cudaGetSymbolAddress(&p_att, g_att);
    float* qkv = (float*)p_qkv;
    float* att = (float*)p_att;

    // 1) QKV projection: [8192,768] @ [768,2304] + bias
    {
        dim3 grid(C3 / BN, BT / BM);
        sgemm_bias_kernel<<<grid, 256>>>(x, W_qkv, b_qkv, qkv, BT, C3, DMODEL);
    }

    // 2) Causal flash attention per (b, h)
    {
        dim3 grid(SEQ / 64, NHEADS, BATCH);
        flash_attn_kernel<<<grid, 64>>>(qkv, att);
    }

    // 3) Output projection: [8192,768] @ [768,768] + bias
    {
        dim3 grid(DMODEL / BN, BT / BM);
        sgemm_bias_kernel<<<grid, 256>>>(att, W_proj, b_proj, out, BT, DMODEL, DMODEL);
    }
}

// round 3
// speedup vs baseline: 2.1514x; 2.1514x over previous
#include <cuda_runtime.h>
#include <cuda_fp16.h>
#include <cuda_bf16.h>
#include <math_constants.h>
#include <cstdint>
#include <cstring>

// Problem constants (fixed by reference setup_inputs)
#define BATCH   2
#define SEQ     4096
#define DMODEL  768
#define NHEADS  12
#define DHEAD   64
#define BT      (BATCH * SEQ)        // 8192
#define C3      (3 * DMODEL)         // 2304

// Scratch (device globals: allocation-free per harness rules)
__device__ float g_qkv[(size_t)BT * C3];     // [B*T, 3C]
__device__ float g_att[(size_t)BT * DMODEL]; // [B*T, C] attention output (pre-proj)

// ---------------------------------------------------------------------------
// PTX helpers
// ---------------------------------------------------------------------------
__device__ __forceinline__ uint32_t f2tf32(float x) {
    uint32_t r;
    asm("cvt.rna.tf32.f32 %0, %1;" : "=r"(r) : "f"(x));
    return r;
}

__device__ __forceinline__ float fast_exp2(float x) {
    float y;
    asm("ex2.approx.f32 %0, %1;" : "=f"(y) : "f"(x));
    return y;
}

// Bit-cast __half2 -> uint32_t (register move in SASS)
__device__ __forceinline__ uint32_t h2_as_u32(__half2 h) {
    uint32_t r;
    memcpy(&r, &h, 4);
    return r;
}

__device__ __forceinline__ void mma_tf32(float c[4], const uint32_t a[4],
                                         uint32_t b0, uint32_t b1) {
    asm volatile(
        "mma.sync.aligned.m16n8k8.row.col.f32.tf32.tf32.f32 "
        "{%0,%1,%2,%3},{%4,%5,%6,%7},{%8,%9},{%0,%1,%2,%3};"
        : "+f"(c[0]), "+f"(c[1]), "+f"(c[2]), "+f"(c[3])
        : "r"(a[0]), "r"(a[1]), "r"(a[2]), "r"(a[3]), "r"(b0), "r"(b1));
}

__device__ __forceinline__ void mma_f16(float c[4], const uint32_t a[4],
                                        uint32_t b0, uint32_t b1) {
    asm volatile(
        "mma.sync.aligned.m16n8k16.row.col.f32.f16.f16.f32 "
        "{%0,%1,%2,%3},{%4,%5,%6,%7},{%8,%9},{%0,%1,%2,%3};"
        : "+f"(c[0]), "+f"(c[1]), "+f"(c[2]), "+f"(c[3])
        : "r"(a[0]), "r"(a[1]), "r"(a[2]), "r"(a[3]), "r"(b0), "r"(b1));
}

__device__ __forceinline__ void ldmatrix_x4_trans(uint32_t& r0, uint32_t& r1,
                                                  uint32_t& r2, uint32_t& r3,
                                                  uint32_t addr) {
    asm volatile(
        "ldmatrix.sync.aligned.m8n8.x4.trans.shared.b16 {%0,%1,%2,%3}, [%4];"
        : "=r"(r0), "=r"(r1), "=r"(r2), "=r"(r3)
        : "r"(addr));
}

// ---------------------------------------------------------------------------
// SGEMM: C[M,N] = A[M,K] @ B[K,N] + bias[N]  (fp32, unchanged from R1)
// ---------------------------------------------------------------------------
#define BM 128
#define BN 128
#define BK 8

__global__ __launch_bounds__(256)
void sgemm_bias_kernel(const float* __restrict__ A,
                       const float* __restrict__ B,
                       const float* __restrict__ bias,
                       float* __restrict__ Cmat,
                       int M, int N, int K)
{
    __shared__ float As[BK][BM];
    __shared__ float Bs[BK][BN];

    const int tid  = threadIdx.x;
    const int brow = blockIdx.y * BM;
    const int bcol = blockIdx.x * BN;

    const int a_row = tid >> 1;
    const int a_col = (tid & 1) * 4;
    const int b_row = tid >> 5;
    const int b_col = (tid & 31) * 4;

    const int t_row = (tid >> 4) * 8;
    const int t_col = (tid & 15) * 8;

    float acc[8][8];
    #pragma unroll
    for (int i = 0; i < 8; i++)
        #pragma unroll
        for (int j = 0; j < 8; j++) acc[i][j] = 0.f;

    for (int k0 = 0; k0 < K; k0 += BK) {
        float4 av = *reinterpret_cast<const float4*>(
            &A[(size_t)(brow + a_row) * K + k0 + a_col]);
        float4 bv = *reinterpret_cast<const float4*>(
            &B[(size_t)(k0 + b_row) * N + bcol + b_col]);

        As[a_col + 0][a_row] = av.x;
        As[a_col + 1][a_row] = av.y;
        As[a_col + 2][a_row] = av.z;
        As[a_col + 3][a_row] = av.w;
        *reinterpret_cast<float4*>(&Bs[b_row][b_col]) = bv;
        __syncthreads();

        #pragma unroll
        for (int k = 0; k < BK; k++) {
            float af[8], bf[8];
            #pragma unroll
            for (int i = 0; i < 8; i++) af[i] = As[k][t_row + i];
            #pragma unroll
            for (int j = 0; j < 8; j++) bf[j] = Bs[k][t_col + j];
            #pragma unroll
            for (int i = 0; i < 8; i++)
                #pragma unroll
                for (int j = 0; j < 8; j++)
                    acc[i][j] += af[i] * bf[j];
        }
        __syncthreads();
    }

    #pragma unroll
    for (int i = 0; i < 8; i++) {
        #pragma unroll
        for (int j = 0; j < 8; j += 4) {
            float4 v;
            v.x = acc[i][j + 0] + bias[bcol + t_col + j + 0];
            v.y = acc[i][j + 1] + bias[bcol + t_col + j + 1];
            v.z = acc[i][j + 2] + bias[bcol + t_col + j + 2];
            v.w = acc[i][j + 3] + bias[bcol + t_col + j + 3];
            *reinterpret_cast<float4*>(
                &Cmat[(size_t)(brow + t_row + i) * N + bcol + t_col + j]) = v;
        }
    }
}

// ---------------------------------------------------------------------------
// Tensor-core flash attention (causal).
// grid = (T/64, H, B), block = 128 (4 warps, 16 q-rows each). KV tile = 64.
//  S = Q·K^T via 3xTF32 mma (fp32-accurate logits), base-2 softmax,
//  O += P·V via fp16 mma (P converted in-place from S accumulators).
// ---------------------------------------------------------------------------
#define KSTRIDE 68   // floats per K row: 68 % 32 == 4 -> conflict-free B frags
#define VSTRIDE 72   // halves per V row: 36 words % 32 == 4 -> ldmatrix clean

__global__ __launch_bounds__(128)
void flash_attn_tc_kernel(const float* __restrict__ qkv, float* __restrict__ out)
{
    __shared__ float  Ks[64][KSTRIDE];
    __shared__ __half Vs[64][VSTRIDE];

    const int qt   = (int)gridDim.x - 1 - (int)blockIdx.x;  // heavy tiles first
    const int h    = blockIdx.y;
    const int b    = blockIdx.z;
    const int tid  = threadIdx.x;
    const int warp = tid >> 5;
    const int lane = tid & 31;
    const int g    = lane >> 2;   // group id (row within 8)
    const int tg   = lane & 3;    // thread in group

    // Fold softmax scale AND log2(e) into Q: softmax invariant to positive
    // linear logit scaling; exp becomes a single ex2.
    const float qscale = 0.125f * 1.4426950408889634f;

    // --- Q fragments, hi/lo tf32 split (A-operand layout of m16n8k8) ---
    uint32_t qh[8][4], ql[8][4];
    {
        const float* qbase =
            qkv + (size_t)(b * SEQ + qt * 64 + warp * 16) * C3 + h * DHEAD;
        #pragma unroll
        for (int ds = 0; ds < 8; ds++) {
            #pragma unroll
            for (int j = 0; j < 4; j++) {
                int row = g + (j & 1) * 8;
                int col = ds * 8 + tg + (j >> 1) * 4;
                float v = qbase[(size_t)row * C3 + col] * qscale;
                uint32_t hi = f2tf32(v);
                qh[ds][j] = hi;
                ql[ds][j] = f2tf32(v - __uint_as_float(hi));
            }
        }
    }

    float oacc[8][4];
    #pragma unroll
    for (int dt = 0; dt < 8; dt++)
        #pragma unroll
        for (int j = 0; j < 4; j++) oacc[dt][j] = 0.f;

    float m0 = -1e30f, m1 = -1e30f, l0 = 0.f, l1 = 0.f;

    for (int kt = 0; kt <= qt; kt++) {
        __syncthreads();
        // Cooperative load: K tile fp32 -> Ks[key][d]; V tile fp16 -> Vs[key][d]
        #pragma unroll
        for (int it = 0; it < 8; it++) {
            int idx = it * 128 + tid;       // 0..1023
            int row = idx >> 4;
            int c4  = idx & 15;
            const float* gb =
                qkv + (size_t)(b * SEQ + kt * 64 + row) * C3 + h * DHEAD;
            float4 kv = *reinterpret_cast<const float4*>(gb + DMODEL + c4 * 4);
            *reinterpret_cast<float4*>(&Ks[row][c4 * 4]) = kv;
            float4 vv = *reinterpret_cast<const float4*>(gb + 2 * DMODEL + c4 * 4);
            __half2 p01 = __floats2half2_rn(vv.x, vv.y);
            __half2 p23 = __floats2half2_rn(vv.z, vv.w);
            *reinterpret_cast<__half2*>(&Vs[row][c4 * 4])     = p01;
            *reinterpret_cast<__half2*>(&Vs[row][c4 * 4 + 2]) = p23;
        }
        __syncthreads();

        // --- S = Qhi*Khi + Qhi*Klo + Qlo*Khi (3xTF32) ---
        float sacc[8][4];
        #pragma unroll
        for (int nt = 0; nt < 8; nt++)
            #pragma unroll
            for (int j = 0; j < 4; j++) sacc[nt][j] = 0.f;

        #pragma unroll
        for (int ds = 0; ds < 8; ds++) {
            #pragma unroll
            for (int nt = 0; nt < 8; nt++) {
                float b0f = Ks[nt * 8 + g][ds * 8 + tg];
                float b1f = Ks[nt * 8 + g][ds * 8 + tg + 4];
                uint32_t b0h = f2tf32(b0f);
                uint32_t b1h = f2tf32(b1f);
                uint32_t b0l = f2tf32(b0f - __uint_as_float(b0h));
                uint32_t b1l = f2tf32(b1f - __uint_as_float(b1h));
                mma_tf32(sacc[nt], qh[ds], b0h, b1h);
                mma_tf32(sacc[nt], qh[ds], b0l, b1l);
                mma_tf32(sacc[nt], ql[ds], b0h, b1h);
            }
        }

        // --- causal mask on diagonal tile ---
        if (kt == qt) {
            #pragma unroll
            for (int nt = 0; nt < 8; nt++) {
                #pragma unroll
                for (int j = 0; j < 4; j++) {
                    int row = warp * 16 + g + (j >> 1) * 8;
                    int col = nt * 8 + 2 * tg + (j & 1);
                    if (col > row) sacc[nt][j] = -1e30f;
                }
            }
        }

        // --- online softmax (base-2) ---
        float mx0 = -1e30f, mx1 = -1e30f;
        #pragma unroll
        for (int nt = 0; nt < 8; nt++) {
            mx0 = fmaxf(mx0, fmaxf(sacc[nt][0], sacc[nt][1]));
            mx1 = fmaxf(mx1, fmaxf(sacc[nt][2], sacc[nt][3]));
        }
        mx0 = fmaxf(mx0, __shfl_xor_sync(0xffffffffu, mx0, 1));
        mx0 = fmaxf(mx0, __shfl_xor_sync(0xffffffffu, mx0, 2));
        mx1 = fmaxf(mx1, __shfl_xor_sync(0xffffffffu, mx1, 1));
        mx1 = fmaxf(mx1, __shfl_xor_sync(0xffffffffu, mx1, 2));

        float mn0 = fmaxf(m0, mx0);
        float mn1 = fmaxf(m1, mx1);
        float al0 = fast_exp2(m0 - mn0);
        float al1 = fast_exp2(m1 - mn1);

        float rs0 = 0.f, rs1 = 0.f;
        #pragma unroll
        for (int nt = 0; nt < 8; nt++) {
            float p0 = fast_exp2(sacc[nt][0] - mn0);
            float p1 = fast_exp2(sacc[nt][1] - mn0);
            float p2 = fast_exp2(sacc[nt][2] - mn1);
            float p3 = fast_exp2(sacc[nt][3] - mn1);
            sacc[nt][0] = p0; sacc[nt][1] = p1;
            sacc[nt][2] = p2; sacc[nt][3] = p3;
            rs0 += p0 + p1;
            rs1 += p2 + p3;
        }
        rs0 += __shfl_xor_sync(0xffffffffu, rs0, 1);
        rs0 += __shfl_xor_sync(0xffffffffu, rs0, 2);
        rs1 += __shfl_xor_sync(0xffffffffu, rs1, 1);
        rs1 += __shfl_xor_sync(0xffffffffu, rs1, 2);

        l0 = l0 * al0 + rs0;
        l1 = l1 * al1 + rs1;
        m0 = mn0;
        m1 = mn1;

        #pragma unroll
        for (int dt = 0; dt < 8; dt++) {
            oacc[dt][0] *= al0; oacc[dt][1] *= al0;
            oacc[dt][2] *= al1; oacc[dt][3] *= al1;
        }

        // --- O += P * V  (fp16 mma; P from S accumulators in-place) ---
        #pragma unroll
        for (int ks = 0; ks < 4; ks++) {
            uint32_t pa[4];
            pa[0] = h2_as_u32(__floats2half2_rn(sacc[2*ks][0],   sacc[2*ks][1]));
            pa[1] = h2_as_u32(__floats2half2_rn(sacc[2*ks][2],   sacc[2*ks][3]));
            pa[2] = h2_as_u32(__floats2half2_rn(sacc[2*ks+1][0], sacc[2*ks+1][1]));
            pa[3] = h2_as_u32(__floats2half2_rn(sacc[2*ks+1][2], sacc[2*ks+1][3]));
            #pragma unroll
            for (int dp = 0; dp < 4; dp++) {
                int krow = ks * 16 + (lane & 15);
                int col  = dp * 16 + ((lane & 16) ? 8 : 0);
                uint32_t addr = (uint32_t)__cvta_generic_to_shared(&Vs[krow][col]);
                uint32_t b0, b1, b2, b3;
                ldmatrix_x4_trans(b0, b1, b2, b3, addr);
                mma_f16(oacc[2 * dp],     pa, b0, b1);
                mma_f16(oacc[2 * dp + 1], pa, b2, b3);
            }
        }
    }

    // --- normalize + write ---
    const float inv0 = 1.f / l0;
    const float inv1 = 1.f / l1;
    float* obase = out + (size_t)(b * SEQ + qt * 64 + warp * 16) * DMODEL + h * DHEAD;
    #pragma unroll
    for (int dt = 0; dt < 8; dt++) {
        int col = dt * 8 + 2 * tg;
        float2 v0 = make_float2(oacc[dt][0] * inv0, oacc[dt][1] * inv0);
        float2 v1 = make_float2(oacc[dt][2] * inv1, oacc[dt][3] * inv1);
        *reinterpret_cast<float2*>(&obase[(size_t)g * DMODEL + col])       = v0;
        *reinterpret_cast<float2*>(&obase[(size_t)(g + 8) * DMODEL + col]) = v1;
    }
}

// ---------------------------------------------------------------------------
// Launch
// ---------------------------------------------------------------------------
extern "C" void kernel_launch(void* const* d_in, const int* in_sizes, int n_in,
                              void* d_out, int out_size)
{
    const float* x      = (const float*)d_in[0];
    const float* W_qkv  = (const float*)d_in[1];
    const float* b_qkv  = (const float*)d_in[2];
    const float* W_proj = (const float*)d_in[3];
    const float* b_proj = (const float*)d_in[4];
    float* out = (float*)d_out;

    void* p_qkv = nullptr;
    void* p_att = nullptr;
    cudaGetSymbolAddress(&p_qkv, g_qkv);
    cudaGetSymbolAddress(&p_att, g_att);
    float* qkv = (float*)p_qkv;
    float* att = (float*)p_att;

    // 1) QKV projection: [8192,768] @ [768,2304] + bias
    {
        dim3 grid(C3 / BN, BT / BM);
        sgemm_bias_kernel<<<grid, 256>>>(x, W_qkv, b_qkv, qkv, BT, C3, DMODEL);
    }

    // 2) Causal flash attention per (b, h) — tensor cores
    {
        dim3 grid(SEQ / 64, NHEADS, BATCH);
        flash_attn_tc_kernel<<<grid, 128>>>(qkv, att);
    }

    // 3) Output projection: [8192,768] @ [768,768] + bias
    {
        dim3 grid(DMODEL / BN, BT / BM);
        sgemm_bias_kernel<<<grid, 256>>>(att, W_proj, b_proj, out, BT, DMODEL, DMODEL);
    }
}

// round 4
// speedup vs baseline: 3.3865x; 1.5741x over previous
#include <cuda_runtime.h>
#include <cuda_fp16.h>
#include <cuda_bf16.h>
#include <math_constants.h>
#include <cstdint>
#include <cstring>

// Problem constants (fixed by reference setup_inputs)
#define BATCH   2
#define SEQ     4096
#define DMODEL  768
#define NHEADS  12
#define DHEAD   64
#define BT      (BATCH * SEQ)        // 8192
#define C3      (3 * DMODEL)         // 2304

// Scratch (device globals: allocation-free per harness rules)
__device__ float g_qkv[(size_t)BT * C3];     // [B*T, 3C]
__device__ float g_att[(size_t)BT * DMODEL]; // [B*T, C] attention output (pre-proj)

// ---------------------------------------------------------------------------
// PTX helpers
// ---------------------------------------------------------------------------
__device__ __forceinline__ uint32_t f2tf32(float x) {
    uint32_t r;
    asm("cvt.rna.tf32.f32 %0, %1;" : "=r"(r) : "f"(x));
    return r;
}

__device__ __forceinline__ float fast_exp2(float x) {
    float y;
    asm("ex2.approx.f32 %0, %1;" : "=f"(y) : "f"(x));
    return y;
}

__device__ __forceinline__ uint32_t h2_as_u32(__half2 h) {
    uint32_t r; memcpy(&r, &h, 4); return r;
}
__device__ __forceinline__ uint32_t bf2_as_u32(__nv_bfloat162 h) {
    uint32_t r; memcpy(&r, &h, 4); return r;
}

__device__ __forceinline__ void mma_tf32(float c[4], const uint32_t a[4],
                                         uint32_t b0, uint32_t b1) {
    asm volatile(
        "mma.sync.aligned.m16n8k8.row.col.f32.tf32.tf32.f32 "
        "{%0,%1,%2,%3},{%4,%5,%6,%7},{%8,%9},{%0,%1,%2,%3};"
        : "+f"(c[0]), "+f"(c[1]), "+f"(c[2]), "+f"(c[3])
        : "r"(a[0]), "r"(a[1]), "r"(a[2]), "r"(a[3]), "r"(b0), "r"(b1));
}

__device__ __forceinline__ void mma_f16(float c[4], const uint32_t a[4],
                                        uint32_t b0, uint32_t b1) {
    asm volatile(
        "mma.sync.aligned.m16n8k16.row.col.f32.f16.f16.f32 "
        "{%0,%1,%2,%3},{%4,%5,%6,%7},{%8,%9},{%0,%1,%2,%3};"
        : "+f"(c[0]), "+f"(c[1]), "+f"(c[2]), "+f"(c[3])
        : "r"(a[0]), "r"(a[1]), "r"(a[2]), "r"(a[3]), "r"(b0), "r"(b1));
}

__device__ __forceinline__ void mma_bf16(float c[4], const uint32_t a[4],
                                         uint32_t b0, uint32_t b1) {
    asm volatile(
        "mma.sync.aligned.m16n8k16.row.col.f32.bf16.bf16.f32 "
        "{%0,%1,%2,%3},{%4,%5,%6,%7},{%8,%9},{%0,%1,%2,%3};"
        : "+f"(c[0]), "+f"(c[1]), "+f"(c[2]), "+f"(c[3])
        : "r"(a[0]), "r"(a[1]), "r"(a[2]), "r"(a[3]), "r"(b0), "r"(b1));
}

__device__ __forceinline__ void ldmatrix_x4(uint32_t& r0, uint32_t& r1,
                                            uint32_t& r2, uint32_t& r3,
                                            uint32_t addr) {
    asm volatile(
        "ldmatrix.sync.aligned.m8n8.x4.shared.b16 {%0,%1,%2,%3}, [%4];"
        : "=r"(r0), "=r"(r1), "=r"(r2), "=r"(r3)
        : "r"(addr));
}

__device__ __forceinline__ void ldmatrix_x4_trans(uint32_t& r0, uint32_t& r1,
                                                  uint32_t& r2, uint32_t& r3,
                                                  uint32_t addr) {
    asm volatile(
        "ldmatrix.sync.aligned.m8n8.x4.trans.shared.b16 {%0,%1,%2,%3}, [%4];"
        : "=r"(r0), "=r"(r1), "=r"(r2), "=r"(r3)
        : "r"(addr));
}

// ---------------------------------------------------------------------------
// bf16x3 tensor-core GEMM: C[M,N] = A[M,K] @ B[K,N] + bias[N]
// A,B split into bf16 hi+lo; C = Ahi*Bhi + Ahi*Blo + Alo*Bhi (fp32 accum).
// Block tile 128x128x32, 256 threads (8 warps, 2x4), warp tile 64x32.
// Requires M%128==0, N%128==0, K%32==0.
// ---------------------------------------------------------------------------
#define GA_STRIDE 40    // halves per A smem row (32 + 8 pad)
#define GB_STRIDE 136   // halves per B smem row (128 + 8 pad)

__global__ __launch_bounds__(256)
void gemm_bf16x3_kernel(const float* __restrict__ A,
                        const float* __restrict__ B,
                        const float* __restrict__ bias,
                        float* __restrict__ Cmat,
                        int M, int N, int K)
{
    __shared__ __nv_bfloat16 Ah[128 * GA_STRIDE];
    __shared__ __nv_bfloat16 Al[128 * GA_STRIDE];
    __shared__ __nv_bfloat16 Bh[32 * GB_STRIDE];
    __shared__ __nv_bfloat16 Bl[32 * GB_STRIDE];

    const int tid  = threadIdx.x;
    const int warp = tid >> 5;
    const int lane = tid & 31;
    const int g    = lane >> 2;
    const int tg   = lane & 3;

    const int brow = blockIdx.y * 128;
    const int bcol = blockIdx.x * 128;
    const int wm   = (warp >> 2) * 64;   // warp row offset
    const int wn   = (warp & 3) * 32;    // warp col offset

    const uint32_t sAh = (uint32_t)__cvta_generic_to_shared(Ah);
    const uint32_t sAl = (uint32_t)__cvta_generic_to_shared(Al);
    const uint32_t sBh = (uint32_t)__cvta_generic_to_shared(Bh);
    const uint32_t sBl = (uint32_t)__cvta_generic_to_shared(Bl);

    float acc[4][4][4];
    #pragma unroll
    for (int mt = 0; mt < 4; mt++)
        #pragma unroll
        for (int nt = 0; nt < 4; nt++)
            #pragma unroll
            for (int j = 0; j < 4; j++) acc[mt][nt][j] = 0.f;

    const int n_stages = K / 32;

    float4 a_reg[4], b_reg[4];
    // Load stage 0
    #pragma unroll
    for (int i = 0; i < 4; i++) {
        int idx = i * 256 + tid;
        a_reg[i] = *reinterpret_cast<const float4*>(
            &A[(size_t)(brow + (idx >> 3)) * K + (idx & 7) * 4]);
        b_reg[i] = *reinterpret_cast<const float4*>(
            &B[(size_t)(idx >> 5) * N + bcol + (idx & 31) * 4]);
    }

    for (int s = 0; s < n_stages; s++) {
        __syncthreads();
        // Store regs -> smem with bf16 hi/lo split
        #pragma unroll
        for (int i = 0; i < 4; i++) {
            int idx = i * 256 + tid;
            {   // A: [row][k] row=idx>>3, k = (idx&7)*4
                float v[4] = {a_reg[i].x, a_reg[i].y, a_reg[i].z, a_reg[i].w};
                __nv_bfloat16 hi[4], lo[4];
                #pragma unroll
                for (int j = 0; j < 4; j++) {
                    hi[j] = __float2bfloat16_rn(v[j]);
                    lo[j] = __float2bfloat16_rn(v[j] - __bfloat162float(hi[j]));
                }
                int off = (idx >> 3) * GA_STRIDE + (idx & 7) * 4;
                uint2 uh, ul;
                memcpy(&uh, hi, 8); memcpy(&ul, lo, 8);
                *reinterpret_cast<uint2*>(&Ah[off]) = uh;
                *reinterpret_cast<uint2*>(&Al[off]) = ul;
            }
            {   // B: [k][n] k=idx>>5, n = (idx&31)*4
                float v[4] = {b_reg[i].x, b_reg[i].y, b_reg[i].z, b_reg[i].w};
                __nv_bfloat16 hi[4], lo[4];
                #pragma unroll
                for (int j = 0; j < 4; j++) {
                    hi[j] = __float2bfloat16_rn(v[j]);
                    lo[j] = __float2bfloat16_rn(v[j] - __bfloat162float(hi[j]));
                }
                int off = (idx >> 5) * GB_STRIDE + (idx & 31) * 4;
                uint2 uh, ul;
                memcpy(&uh, hi, 8); memcpy(&ul, lo, 8);
                *reinterpret_cast<uint2*>(&Bh[off]) = uh;
                *reinterpret_cast<uint2*>(&Bl[off]) = ul;
            }
        }
        __syncthreads();

        // Prefetch next stage (LDG latency hidden under mma below)
        if (s + 1 < n_stages) {
            int k0 = (s + 1) * 32;
            #pragma unroll
            for (int i = 0; i < 4; i++) {
                int idx = i * 256 + tid;
                a_reg[i] = *reinterpret_cast<const float4*>(
                    &A[(size_t)(brow + (idx >> 3)) * K + k0 + (idx & 7) * 4]);
                b_reg[i] = *reinterpret_cast<const float4*>(
                    &B[(size_t)(k0 + (idx >> 5)) * N + bcol + (idx & 31) * 4]);
            }
        }

        // mma over 2 k16 steps
        #pragma unroll
        for (int ks = 0; ks < 2; ks++) {
            // B fragments: 2 n16 groups, hi+lo
            uint32_t bhf[2][4], blf[2][4];
            #pragma unroll
            for (int ng = 0; ng < 2; ng++) {
                uint32_t boff = (uint32_t)(
                    (ks * 16 + (lane & 15)) * GB_STRIDE +
                    wn + ng * 16 + ((lane & 16) ? 8 : 0)) * 2u;
                ldmatrix_x4_trans(bhf[ng][0], bhf[ng][1], bhf[ng][2], bhf[ng][3],
                                  sBh + boff);
                ldmatrix_x4_trans(blf[ng][0], blf[ng][1], blf[ng][2], blf[ng][3],
                                  sBl + boff);
            }
            #pragma unroll
            for (int mt = 0; mt < 4; mt++) {
                uint32_t ahf[4], alf[4];
                uint32_t aoff = (uint32_t)(
                    (wm + mt * 16 + (lane & 15)) * GA_STRIDE +
                    ks * 16 + ((lane & 16) ? 8 : 0)) * 2u;
                ldmatrix_x4(ahf[0], ahf[1], ahf[2], ahf[3], sAh + aoff);
                ldmatrix_x4(alf[0], alf[1], alf[2], alf[3], sAl + aoff);
                #pragma unroll
                for (int ng = 0; ng < 2; ng++) {
                    #pragma unroll
                    for (int hh = 0; hh < 2; hh++) {
                        int nt = ng * 2 + hh;
                        uint32_t b0h = bhf[ng][2 * hh], b1h = bhf[ng][2 * hh + 1];
                        uint32_t b0l = blf[ng][2 * hh], b1l = blf[ng][2 * hh + 1];
                        mma_bf16(acc[mt][nt], ahf, b0h, b1h);
                        mma_bf16(acc[mt][nt], ahf, b0l, b1l);
                        mma_bf16(acc[mt][nt], alf, b0h, b1h);
                    }
                }
            }
        }
    }

    // Epilogue: bias + store
    #pragma unroll
    for (int mt = 0; mt < 4; mt++) {
        #pragma unroll
        for (int nt = 0; nt < 4; nt++) {
            int row0 = brow + wm + mt * 16 + g;
            int col  = bcol + wn + nt * 8 + 2 * tg;
            float b0 = bias[col], b1 = bias[col + 1];
            float2 v0 = make_float2(acc[mt][nt][0] + b0, acc[mt][nt][1] + b1);
            float2 v1 = make_float2(acc[mt][nt][2] + b0, acc[mt][nt][3] + b1);
            *reinterpret_cast<float2*>(&Cmat[(size_t)row0 * N + col])       = v0;
            *reinterpret_cast<float2*>(&Cmat[(size_t)(row0 + 8) * N + col]) = v1;
        }
    }
}

// ---------------------------------------------------------------------------
// Tensor-core flash attention (causal). Unchanged from R3 (passing, 2.3e-4).
// ---------------------------------------------------------------------------
#define KSTRIDE 68   // floats per K row: 68 % 32 == 4 -> conflict-free B frags
#define VSTRIDE 72   // halves per V row: 36 words % 32 == 4 -> ldmatrix clean

__global__ __launch_bounds__(128)
void flash_attn_tc_kernel(const float* __restrict__ qkv, float* __restrict__ out)
{
    __shared__ float  Ks[64][KSTRIDE];
    __shared__ __half Vs[64][VSTRIDE];

    const int qt   = (int)gridDim.x - 1 - (int)blockIdx.x;  // heavy tiles first
    const int h    = blockIdx.y;
    const int b    = blockIdx.z;
    const int tid  = threadIdx.x;
    const int warp = tid >> 5;
    const int lane = tid & 31;
    const int g    = lane >> 2;
    const int tg   = lane & 3;

    const float qscale = 0.125f * 1.4426950408889634f;

    uint32_t qh[8][4], ql[8][4];
    {
        const float* qbase =
            qkv + (size_t)(b * SEQ + qt * 64 + warp * 16) * C3 + h * DHEAD;
        #pragma unroll
        for (int ds = 0; ds < 8; ds++) {
            #pragma unroll
            for (int j = 0; j < 4; j++) {
                int row = g + (j & 1) * 8;
                int col = ds * 8 + tg + (j >> 1) * 4;
                float v = qbase[(size_t)row * C3 + col] * qscale;
                uint32_t hi = f2tf32(v);
                qh[ds][j] = hi;
                ql[ds][j] = f2tf32(v - __uint_as_float(hi));
            }
        }
    }

    float oacc[8][4];
    #pragma unroll
    for (int dt = 0; dt < 8; dt++)
        #pragma unroll
        for (int j = 0; j < 4; j++) oacc[dt][j] = 0.f;

    float m0 = -1e30f, m1 = -1e30f, l0 = 0.f, l1 = 0.f;

    for (int kt = 0; kt <= qt; kt++) {
        __syncthreads();
        #pragma unroll
        for (int it = 0; it < 8; it++) {
            int idx = it * 128 + tid;
            int row = idx >> 4;
            int c4  = idx & 15;
            const float* gb =
                qkv + (size_t)(b * SEQ + kt * 64 + row) * C3 + h * DHEAD;
            float4 kv = *reinterpret_cast<const float4*>(gb + DMODEL + c4 * 4);
            *reinterpret_cast<float4*>(&Ks[row][c4 * 4]) = kv;
            float4 vv = *reinterpret_cast<const float4*>(gb + 2 * DMODEL + c4 * 4);
            __half2 p01 = __floats2half2_rn(vv.x, vv.y);
            __half2 p23 = __floats2half2_rn(vv.z, vv.w);
            *reinterpret_cast<__half2*>(&Vs[row][c4 * 4])     = p01;
            *reinterpret_cast<__half2*>(&Vs[row][c4 * 4 + 2]) = p23;
        }
        __syncthreads();

        float sacc[8][4];
        #pragma unroll
        for (int nt = 0; nt < 8; nt++)
            #pragma unroll
            for (int j = 0; j < 4; j++) sacc[nt][j] = 0.f;

        #pragma unroll
        for (int ds = 0; ds < 8; ds++) {
            #pragma unroll
            for (int nt = 0; nt < 8; nt++) {
                float b0f = Ks[nt * 8 + g][ds * 8 + tg];
                float b1f = Ks[nt * 8 + g][ds * 8 + tg + 4];
                uint32_t b0h = f2tf32(b0f);
                uint32_t b1h = f2tf32(b1f);
                uint32_t b0l = f2tf32(b0f - __uint_as_float(b0h));
                uint32_t b1l = f2tf32(b1f - __uint_as_float(b1h));
                mma_tf32(sacc[nt], qh[ds], b0h, b1h);
                mma_tf32(sacc[nt], qh[ds], b0l, b1l);
                mma_tf32(sacc[nt], ql[ds], b0h, b1h);
            }
        }

        if (kt == qt) {
            #pragma unroll
            for (int nt = 0; nt < 8; nt++) {
                #pragma unroll
                for (int j = 0; j < 4; j++) {
                    int row = warp * 16 + g + (j >> 1) * 8;
                    int col = nt * 8 + 2 * tg + (j & 1);
                    if (col > row) sacc[nt][j] = -1e30f;
                }
            }
        }

        float mx0 = -1e30f, mx1 = -1e30f;
        #pragma unroll
        for (int nt = 0; nt < 8; nt++) {
            mx0 = fmaxf(mx0, fmaxf(sacc[nt][0], sacc[nt][1]));
            mx1 = fmaxf(mx1, fmaxf(sacc[nt][2], sacc[nt][3]));
        }
        mx0 = fmaxf(mx0, __shfl_xor_sync(0xffffffffu, mx0, 1));
        mx0 = fmaxf(mx0, __shfl_xor_sync(0xffffffffu, mx0, 2));
        mx1 = fmaxf(mx1, __shfl_xor_sync(0xffffffffu, mx1, 1));
        mx1 = fmaxf(mx1, __shfl_xor_sync(0xffffffffu, mx1, 2));

        float mn0 = fmaxf(m0, mx0);
        float mn1 = fmaxf(m1, mx1);
        float al0 = fast_exp2(m0 - mn0);
        float al1 = fast_exp2(m1 - mn1);

        float rs0 = 0.f, rs1 = 0.f;
        #pragma unroll
        for (int nt = 0; nt < 8; nt++) {
            float p0 = fast_exp2(sacc[nt][0] - mn0);
            float p1 = fast_exp2(sacc[nt][1] - mn0);
            float p2 = fast_exp2(sacc[nt][2] - mn1);
            float p3 = fast_exp2(sacc[nt][3] - mn1);
            sacc[nt][0] = p0; sacc[nt][1] = p1;
            sacc[nt][2] = p2; sacc[nt][3] = p3;
            rs0 += p0 + p1;
            rs1 += p2 + p3;
        }
        rs0 += __shfl_xor_sync(0xffffffffu, rs0, 1);
        rs0 += __shfl_xor_sync(0xffffffffu, rs0, 2);
        rs1 += __shfl_xor_sync(0xffffffffu, rs1, 1);
        rs1 += __shfl_xor_sync(0xffffffffu, rs1, 2);

        l0 = l0 * al0 + rs0;
        l1 = l1 * al1 + rs1;
        m0 = mn0;
        m1 = mn1;

        #pragma unroll
        for (int dt = 0; dt < 8; dt++) {
            oacc[dt][0] *= al0; oacc[dt][1] *= al0;
            oacc[dt][2] *= al1; oacc[dt][3] *= al1;
        }

        #pragma unroll
        for (int ks = 0; ks < 4; ks++) {
            uint32_t pa[4];
            pa[0] = h2_as_u32(__floats2half2_rn(sacc[2*ks][0],   sacc[2*ks][1]));
            pa[1] = h2_as_u32(__floats2half2_rn(sacc[2*ks][2],   sacc[2*ks][3]));
            pa[2] = h2_as_u32(__floats2half2_rn(sacc[2*ks+1][0], sacc[2*ks+1][1]));
            pa[3] = h2_as_u32(__floats2half2_rn(sacc[2*ks+1][2], sacc[2*ks+1][3]));
            #pragma unroll
            for (int dp = 0; dp < 4; dp++) {
                int krow = ks * 16 + (lane & 15);
                int col  = dp * 16 + ((lane & 16) ? 8 : 0);
                uint32_t addr = (uint32_t)__cvta_generic_to_shared(&Vs[krow][col]);
                uint32_t b0, b1, b2, b3;
                ldmatrix_x4_trans(b0, b1, b2, b3, addr);
                mma_f16(oacc[2 * dp],     pa, b0, b1);
                mma_f16(oacc[2 * dp + 1], pa, b2, b3);
            }
        }
    }

    const float inv0 = 1.f / l0;
    const float inv1 = 1.f / l1;
    float* obase = out + (size_t)(b * SEQ + qt * 64 + warp * 16) * DMODEL + h * DHEAD;
    #pragma unroll
    for (int dt = 0; dt < 8; dt++) {
        int col = dt * 8 + 2 * tg;
        float2 v0 = make_float2(oacc[dt][0] * inv0, oacc[dt][1] * inv0);
        float2 v1 = make_float2(oacc[dt][2] * inv1, oacc[dt][3] * inv1);
        *reinterpret_cast<float2*>(&obase[(size_t)g * DMODEL + col])       = v0;
        *reinterpret_cast<float2*>(&obase[(size_t)(g + 8) * DMODEL + col]) = v1;
    }
}

// ---------------------------------------------------------------------------
// Launch
// ---------------------------------------------------------------------------
extern "C" void kernel_launch(void* const* d_in, const int* in_sizes, int n_in,
                              void* d_out, int out_size)
{
    const float* x      = (const float*)d_in[0];
    const float* W_qkv  = (const float*)d_in[1];
    const float* b_qkv  = (const float*)d_in[2];
    const float* W_proj = (const float*)d_in[3];
    const float* b_proj = (const float*)d_in[4];
    float* out = (float*)d_out;

    void* p_qkv = nullptr;
    void* p_att = nullptr;
    cudaGetSymbolAddress(&p_qkv, g_qkv);
    cudaGetSymbolAddress(&p_att, g_att);
    float* qkv = (float*)p_qkv;
    float* att = (float*)p_att;

    // 1) QKV projection: [8192,768] @ [768,2304] + bias (bf16x3 tensor cores)
    {
        dim3 grid(C3 / 128, BT / 128);
        gemm_bf16x3_kernel<<<grid, 256>>>(x, W_qkv, b_qkv, qkv, BT, C3, DMODEL);
    }

    // 2) Causal flash attention per (b, h) — tensor cores
    {
        dim3 grid(SEQ / 64, NHEADS, BATCH);
        flash_attn_tc_kernel<<<grid, 128>>>(qkv, att);
    }

    // 3) Output projection: [8192,768] @ [768,768] + bias (bf16x3 tensor cores)
    {
        dim3 grid(DMODEL / 128, BT / 128);
        gemm_bf16x3_kernel<<<grid, 256>>>(att, W_proj, b_proj, out, BT, DMODEL, DMODEL);
    }
}